// round 5
// baseline (speedup 1.0000x reference)
#include <cuda_runtime.h>
#include <cstdint>

#define SEQ   4096
#define EMB   300
#define K_IN  600      // 2*EMB
#define HID   500
#define JPAD  512      // padded hidden
#define GPAD  2048     // padded gate rows (4*JPAD)
#define NCTA  64       // recurrence CTAs: 64 x 8 warps = 512 warps = JPAD units
#define CTHR  256

// ---------------- scratch (static device globals; no allocation) -----------
__device__ float g_X[(size_t)SEQ * K_IN];                  // gathered inputs
__device__ float g_pre[(size_t)SEQ * GPAD];                // pre-activations, remapped
__device__ unsigned long long g_ht[2][JPAD];               // tagged h: {tag<<32 | f32}

// ---------------- fast activations (MUFU ex2/rcp) --------------------------
__device__ __forceinline__ float fex2(float x){ float y; asm("ex2.approx.f32 %0,%1;":"=f"(y):"f"(x)); return y; }
__device__ __forceinline__ float frcp(float x){ float y; asm("rcp.approx.f32 %0,%1;":"=f"(y):"f"(x)); return y; }
__device__ __forceinline__ float fsig (float x){ return frcp(1.0f + fex2(-1.44269504f * x)); }
__device__ __forceinline__ float ftanh(float x){ float e = fex2(2.88539008f * x); return 1.0f - 2.0f * frcp(e + 1.0f); }

__device__ __forceinline__ unsigned long long pack2(float a, float b){
    unsigned long long r; asm("mov.b64 %0,{%1,%2};" : "=l"(r) : "f"(a), "f"(b)); return r;
}
__device__ __forceinline__ void fma2(unsigned long long& acc, unsigned long long a, unsigned long long b){
    asm("fma.rn.f32x2 %0, %1, %2, %0;" : "+l"(acc) : "l"(a), "l"(b));
}

// tagged-packet helpers ------------------------------------------------------
__device__ __forceinline__ void ld_pair_cg(const unsigned long long* p,
                                           unsigned long long& a, unsigned long long& b){
    asm volatile("ld.global.cg.v2.u64 {%0,%1}, [%2];"
                 : "=l"(a), "=l"(b) : "l"(p) : "memory");
}
__device__ __forceinline__ void st_pkt_cg(unsigned long long* p, unsigned long long v){
    asm volatile("st.global.cg.u64 [%0], %1;" :: "l"(p), "l"(v) : "memory");
}
__device__ __forceinline__ int   pkt_tag(unsigned long long v){ return (int)(v >> 32); }
__device__ __forceinline__ float pkt_val(unsigned long long v){ return __uint_as_float((unsigned)v); }
__device__ __forceinline__ unsigned long long mk_pkt(int tag, float h){
    return ((unsigned long long)(unsigned)tag << 32) | __float_as_uint(h);
}
__device__ __forceinline__ bool fresh2(unsigned long long a, unsigned long long b, int t){
    return (pkt_tag(a) == t) & (pkt_tag(b) == t);
}

// 2-deep pipelined poll: keeps a second load in flight while checking the
// first; detection lag after arrival ~ half an L2 round trip.
__device__ __forceinline__ float2 poll_pair(const unsigned long long* q, int t){
    unsigned long long a0, b0, a1, b1;
    ld_pair_cg(q, a0, b0);
    ld_pair_cg(q, a1, b1);
    for (;;) {
        if (fresh2(a0, b0, t)) return make_float2(pkt_val(a0), pkt_val(b0));
        ld_pair_cg(q, a0, b0);
        if (fresh2(a1, b1, t)) return make_float2(pkt_val(a1), pkt_val(b1));
        ld_pair_cg(q, a1, b1);
    }
}

// ---------------- kernel 1: seed step-0 h and invalidate buffer 1 -----------
__global__ void k_reset()
{
    int i = threadIdx.x;
    if (i < JPAD) {
        g_ht[0][i] = mk_pkt(0, 0.0f);     // h(0) = 0, tag 0
        g_ht[1][i] = mk_pkt(-1, 0.0f);    // invalid
    }
}

// ---------------- kernel 2: embedding gather + concat -----------------------
__global__ void k_gather(const int* __restrict__ words, const int* __restrict__ labels,
                         const float* __restrict__ ew,  const float* __restrict__ ee)
{
    int id = blockIdx.x * blockDim.x + threadIdx.x;
    int t = id / K_IN;
    int k = id - t * K_IN;
    float v = (k < EMB) ? ew[(size_t)words[t]  * EMB + k]
                        : ee[(size_t)labels[t] * EMB + (k - EMB)];
    g_X[id] = v;
}

// ---------------- kernel 3: pre = X @ W_ih^T + (b_ih + b_hh), remapped ------
// Global gate row R in [0,2048):
//   unit j = ((R>>5)<<3) | ((R>>2)&7),  gate g = R&3  (4 gates contiguous)
__global__ void __launch_bounds__(256) k_gemm(const float* __restrict__ W,
                                              const float* __restrict__ bi,
                                              const float* __restrict__ bh)
{
    __shared__ float xs[8][64];
    __shared__ float ws[8][68];

    int t0 = blockIdx.x * 64;
    int R0 = blockIdx.y * 64;
    int tid = threadIdx.x;
    int tx = tid & 15;
    int ty = tid >> 4;

    float acc[4][4];
#pragma unroll
    for (int i = 0; i < 4; i++)
#pragma unroll
        for (int j = 0; j < 4; j++) acc[i][j] = 0.0f;

    for (int k0 = 0; k0 < K_IN; k0 += 8) {
#pragma unroll
        for (int p = 0; p < 2; p++) {
            int e  = tid + p * 256;
            int kk = e >> 6;
            int rr = e & 63;
            int R = R0 + rr;
            int g  = R & 3;
            int j  = ((R >> 5) << 3) | ((R >> 2) & 7);
            float wv = 0.0f;
            if (j < HID) wv = W[(size_t)(g * HID + j) * K_IN + (k0 + kk)];
            ws[kk][rr] = wv;
            xs[kk][rr] = g_X[(size_t)(t0 + rr) * K_IN + (k0 + kk)];
        }
        __syncthreads();
#pragma unroll
        for (int kk = 0; kk < 8; kk++) {
            float a[4], x[4];
#pragma unroll
            for (int i = 0; i < 4; i++) a[i] = ws[kk][ty + 16 * i];
#pragma unroll
            for (int j = 0; j < 4; j++) x[j] = xs[kk][tx + 16 * j];
#pragma unroll
            for (int i = 0; i < 4; i++)
#pragma unroll
                for (int j = 0; j < 4; j++) acc[i][j] += a[i] * x[j];
        }
        __syncthreads();
    }

#pragma unroll
    for (int i = 0; i < 4; i++) {
        int R = R0 + ty + 16 * i;
        int g  = R & 3;
        int j  = ((R >> 5) << 3) | ((R >> 2) & 7);
        bool valid = (j < HID);
        float bb = valid ? (bi[g * HID + j] + bh[g * HID + j]) : 0.0f;
#pragma unroll
        for (int jx = 0; jx < 4; jx++) {
            int t = t0 + tx + 16 * jx;
            g_pre[(size_t)t * GPAD + R] = valid ? (acc[i][jx] + bb) : 0.0f;
        }
    }
}

// ---------------- kernel 4: tagged-data LSTM, CTA-cooperative staging --------
// 64 CTAs x 8 warps; warp w of CTA blk owns hidden unit j = blk*8 + w.
// Per step:
//   - lanes 1..31 each poll one (lane 31: two) 16B tagged pairs of chunk w,
//     depositing into double-buffered smem the moment each pair is fresh
//     (no votes, no reconvergence; lane 0 never polls -- it is the busy lane)
//   - single __syncthreads
//   - all warps: 8x LDS.64 + 32x fma.f32x2 vs register W_hh, 5-stage
//     butterfly (4 gates, ILP), lane0 activations + cell update, one weak
//     8B tagged store publishes h
__global__ void __launch_bounds__(CTHR, 1)
k_lstm(const float* __restrict__ Whh, const float* __restrict__ fcw,
       const float* __restrict__ fcb, float* __restrict__ out)
{
    __shared__ float sh_h[2][JPAD];     // double buffer

    const int tid  = threadIdx.x;
    const int blk  = blockIdx.x;
    const int w    = tid >> 5;          // warp id = unit within CTA + poll chunk
    const int lane = tid & 31;
    const int j    = blk * 8 + w;       // this warp's hidden unit

    // register-resident W_hh: 4 gates x 8 packed pairs, k = 2*lane + 64*m
    unsigned long long w2[4][8];
#pragma unroll
    for (int g = 0; g < 4; g++) {
#pragma unroll
        for (int m = 0; m < 8; m++) {
            int k = 2 * lane + 64 * m;
            float a = 0.0f, b = 0.0f;
            if (j < HID) {
                const float* row = Whh + (size_t)(g * HID + j) * HID;
                if (k     < HID) a = row[k];
                if (k + 1 < HID) b = row[k + 1];
            }
            w2[g][m] = pack2(a, b);
        }
    }

    float c = 0.0f;                                  // cell state (lane 0)
    const float* preB = g_pre + (size_t)blk * 32 + w * 4;

    // poll assignment: lane l>=1 handles pair (l-1) of chunk w; lane 31 also
    // handles pair 31. (u64 index = 64*w + 2*pair)
    const int p0 = lane - 1;

    // software-pipelined pre prefetch
    float4 pv = make_float4(0.f, 0.f, 0.f, 0.f);
    if (lane == 0) pv = __ldg((const float4*)(preB));

#pragma unroll 1
    for (int t = 0; t < SEQ; t++) {
        // issue next step's pre load early (hides under this step's poll)
        float4 pv_n = make_float4(0.f, 0.f, 0.f, 0.f);
        if (lane == 0) {
            size_t tn = (t + 1 < SEQ) ? (size_t)(t + 1) : (size_t)(SEQ - 1);
            pv_n = __ldg((const float4*)(preB + tn * GPAD));
        }

        // ---- poll own pairs of h(t); deposit immediately on freshness -----
        const unsigned long long* hb = g_ht[t & 1];
        float2* shb = (float2*)sh_h[t & 1];
        if (lane >= 1) {
            float2 v = poll_pair(&hb[64 * w + 2 * p0], t);
            shb[32 * w + p0] = v;
            if (lane == 31) {
                float2 v2 = poll_pair(&hb[64 * w + 62], t);
                shb[32 * w + 31] = v2;
            }
        }
        __syncthreads();

        // ---- matvec: 4 gates x 8 packed FMAs from smem --------------------
        unsigned long long acc2[4] = {0ull, 0ull, 0ull, 0ull};
#pragma unroll
        for (int m = 0; m < 8; m++) {
            float2 hv = shb[lane + 32 * m];
            unsigned long long h2 = pack2(hv.x, hv.y);
#pragma unroll
            for (int g = 0; g < 4; g++)
                fma2(acc2[g], w2[g][m], h2);
        }

        float s[4];
#pragma unroll
        for (int g = 0; g < 4; g++) {
            float lo = __uint_as_float((unsigned)acc2[g]);
            float hi = __uint_as_float((unsigned)(acc2[g] >> 32));
            s[g] = lo + hi;
        }
#pragma unroll
        for (int d = 16; d >= 1; d >>= 1)
#pragma unroll
            for (int g = 0; g < 4; g++)
                s[g] += __shfl_xor_sync(0xffffffffu, s[g], d);

        // ---- cell update + publish (lane 0, one 8B weak tagged store) -----
        if (lane == 0) {
            float gi = fsig (s[0] + pv.x);
            float gf = fsig (s[1] + pv.y);
            float gg = ftanh(s[2] + pv.z);
            float go = fsig (s[3] + pv.w);
            c = gf * c + gi * gg;
            float h = go * ftanh(c);
            st_pkt_cg(&g_ht[(t + 1) & 1][j], mk_pkt(t + 1, h));
        }
        pv = pv_n;
    }

    // ---------------- final FC: out[20] = fc_w @ h(SEQ) + fc_b (CTA 0) ------
    if (blk == 0) {
        const unsigned long long* hb = g_ht[SEQ & 1];
        float2* shb = (float2*)sh_h[0];
        float2 v = poll_pair(&hb[64 * w + 2 * lane], SEQ);
        shb[32 * w + lane] = v;
        __syncthreads();

        const float* hL = sh_h[0];
#pragma unroll 1
        for (int o = w; o < 20; o += 8) {
            float a = 0.0f;
#pragma unroll
            for (int m = 0; m < 16; m++) {
                int k = lane + 32 * m;
                if (k < HID) a += fcw[(size_t)o * HID + k] * hL[k];
            }
#pragma unroll
            for (int d = 16; d >= 1; d >>= 1)
                a += __shfl_xor_sync(0xffffffffu, a, d);
            if (lane == 0) out[o] = a + fcb[o];
        }
    }
}

// ---------------- launch ----------------------------------------------------
extern "C" void kernel_launch(void* const* d_in, const int* in_sizes, int n_in,
                              void* d_out, int out_size)
{
    const int*   words  = (const int*)  d_in[0];
    const int*   labels = (const int*)  d_in[1];
    const float* ew     = (const float*)d_in[2];
    const float* ee     = (const float*)d_in[3];
    const float* W_ih   = (const float*)d_in[4];
    const float* W_hh   = (const float*)d_in[5];
    const float* b_ih   = (const float*)d_in[6];
    const float* b_hh   = (const float*)d_in[7];
    const float* fc_w   = (const float*)d_in[8];
    const float* fc_b   = (const float*)d_in[9];
    float* out = (float*)d_out;

    k_reset<<<1, JPAD>>>();
    k_gather<<<(SEQ * K_IN) / 1024, 1024>>>(words, labels, ew, ee);
    k_gemm<<<dim3(SEQ / 64, GPAD / 64), 256>>>(W_ih, b_ih, b_hh);
    k_lstm<<<NCTA, CTHR>>>(W_hh, fc_w, fc_b, out);
}

// round 13
// speedup vs baseline: 1.6732x; 1.6732x over previous
#include <cuda_runtime.h>
#include <cstdint>

#define SEQ   4096
#define EMB   300
#define K_IN  600      // 2*EMB
#define HID   500
#define JPAD  512      // padded hidden
#define GPAD  2048     // padded gate rows (4*JPAD)
#define NCTA  64       // recurrence CTAs: 64 x 8 warps = 512 warps = JPAD units
#define CTHR  256

// ---------------- scratch (static device globals; no allocation) -----------
__device__ float g_X[(size_t)SEQ * K_IN];                  // gathered inputs
__device__ float g_pre[(size_t)SEQ * GPAD];                // pre-activations, remapped
__device__ unsigned long long g_ht[2][JPAD];               // tagged h: {tag<<32 | f32}

// ---------------- fast activations (MUFU ex2/rcp) --------------------------
__device__ __forceinline__ float fex2(float x){ float y; asm("ex2.approx.f32 %0,%1;":"=f"(y):"f"(x)); return y; }
__device__ __forceinline__ float frcp(float x){ float y; asm("rcp.approx.f32 %0,%1;":"=f"(y):"f"(x)); return y; }
__device__ __forceinline__ float fsig (float x){ return frcp(1.0f + fex2(-1.44269504f * x)); }
__device__ __forceinline__ float ftanh(float x){ float e = fex2(2.88539008f * x); return 1.0f - 2.0f * frcp(e + 1.0f); }

__device__ __forceinline__ unsigned long long pack2(float a, float b){
    unsigned long long r; asm("mov.b64 %0,{%1,%2};" : "=l"(r) : "f"(a), "f"(b)); return r;
}
__device__ __forceinline__ void fma2(unsigned long long& acc, unsigned long long a, unsigned long long b){
    asm("fma.rn.f32x2 %0, %1, %2, %0;" : "+l"(acc) : "l"(a), "l"(b));
}

// tagged-packet helpers ------------------------------------------------------
__device__ __forceinline__ void ld_pair_cg(const unsigned long long* p,
                                           unsigned long long& a, unsigned long long& b){
    asm volatile("ld.global.cg.v2.u64 {%0,%1}, [%2];"
                 : "=l"(a), "=l"(b) : "l"(p) : "memory");
}
__device__ __forceinline__ void st_pkt_cg(unsigned long long* p, unsigned long long v){
    asm volatile("st.global.cg.u64 [%0], %1;" :: "l"(p), "l"(v) : "memory");
}
__device__ __forceinline__ int   pkt_tag(unsigned long long v){ return (int)(v >> 32); }
__device__ __forceinline__ float pkt_val(unsigned long long v){ return __uint_as_float((unsigned)v); }
__device__ __forceinline__ unsigned long long mk_pkt(int tag, float h){
    return ((unsigned long long)(unsigned)tag << 32) | __float_as_uint(h);
}

// ---------------- kernel 1: seed step-0 h and invalidate buffer 1 -----------
__global__ void k_reset()
{
    int i = threadIdx.x;
    if (i < JPAD) {
        g_ht[0][i] = mk_pkt(0, 0.0f);     // h(0) = 0, tag 0
        g_ht[1][i] = mk_pkt(-1, 0.0f);    // invalid
    }
}

// ---------------- kernel 2: embedding gather + concat -----------------------
__global__ void k_gather(const int* __restrict__ words, const int* __restrict__ labels,
                         const float* __restrict__ ew,  const float* __restrict__ ee)
{
    int id = blockIdx.x * blockDim.x + threadIdx.x;
    int t = id / K_IN;
    int k = id - t * K_IN;
    float v = (k < EMB) ? ew[(size_t)words[t]  * EMB + k]
                        : ee[(size_t)labels[t] * EMB + (k - EMB)];
    g_X[id] = v;
}

// ---------------- kernel 3: pre = X @ W_ih^T + (b_ih + b_hh), remapped ------
// Global gate row R in [0,2048):
//   unit j = ((R>>5)<<3) | ((R>>2)&7),  gate g = R&3  (4 gates contiguous)
__global__ void __launch_bounds__(256) k_gemm(const float* __restrict__ W,
                                              const float* __restrict__ bi,
                                              const float* __restrict__ bh)
{
    __shared__ float xs[8][64];
    __shared__ float ws[8][68];

    int t0 = blockIdx.x * 64;
    int R0 = blockIdx.y * 64;
    int tid = threadIdx.x;
    int tx = tid & 15;
    int ty = tid >> 4;

    float acc[4][4];
#pragma unroll
    for (int i = 0; i < 4; i++)
#pragma unroll
        for (int j = 0; j < 4; j++) acc[i][j] = 0.0f;

    for (int k0 = 0; k0 < K_IN; k0 += 8) {
#pragma unroll
        for (int p = 0; p < 2; p++) {
            int e  = tid + p * 256;
            int kk = e >> 6;
            int rr = e & 63;
            int R = R0 + rr;
            int g  = R & 3;
            int j  = ((R >> 5) << 3) | ((R >> 2) & 7);
            float wv = 0.0f;
            if (j < HID) wv = W[(size_t)(g * HID + j) * K_IN + (k0 + kk)];
            ws[kk][rr] = wv;
            xs[kk][rr] = g_X[(size_t)(t0 + rr) * K_IN + (k0 + kk)];
        }
        __syncthreads();
#pragma unroll
        for (int kk = 0; kk < 8; kk++) {
            float a[4], x[4];
#pragma unroll
            for (int i = 0; i < 4; i++) a[i] = ws[kk][ty + 16 * i];
#pragma unroll
            for (int j = 0; j < 4; j++) x[j] = xs[kk][tx + 16 * j];
#pragma unroll
            for (int i = 0; i < 4; i++)
#pragma unroll
                for (int j = 0; j < 4; j++) acc[i][j] += a[i] * x[j];
        }
        __syncthreads();
    }

#pragma unroll
    for (int i = 0; i < 4; i++) {
        int R = R0 + ty + 16 * i;
        int g  = R & 3;
        int j  = ((R >> 5) << 3) | ((R >> 2) & 7);
        bool valid = (j < HID);
        float bb = valid ? (bi[g * HID + j] + bh[g * HID + j]) : 0.0f;
#pragma unroll
        for (int jx = 0; jx < 4; jx++) {
            int t = t0 + tx + 16 * jx;
            g_pre[(size_t)t * GPAD + R] = valid ? (acc[i][jx] + bb) : 0.0f;
        }
    }
}

// ---------------- kernel 4: tagged-data LSTM, CTA-cooperative staging --------
// EXACT R4 sync structure and poll (proven 7.7ms). One change, orthogonal to
// synchronization: the 4 gate activations are computed in parallel on lanes
// 0-3 (each loads its own pre scalar from the same 16B sector), then lane 0
// gathers via 3 SHFLs for the cell update + tagged publish. This shortens the
// serial lane-0 tail (~160 -> ~70 cyc) that gates every other CTA's poll.
__global__ void __launch_bounds__(CTHR, 1)
k_lstm(const float* __restrict__ Whh, const float* __restrict__ fcw,
       const float* __restrict__ fcb, float* __restrict__ out)
{
    __shared__ float sh_h[JPAD];

    const int tid  = threadIdx.x;
    const int blk  = blockIdx.x;
    const int w    = tid >> 5;          // warp id = unit within CTA + poll chunk
    const int lane = tid & 31;
    const int j    = blk * 8 + w;       // this warp's hidden unit

    // register-resident W_hh: 4 gates x 8 packed pairs, k = 2*lane + 64*m
    unsigned long long w2[4][8];
#pragma unroll
    for (int g = 0; g < 4; g++) {
#pragma unroll
        for (int m = 0; m < 8; m++) {
            int k = 2 * lane + 64 * m;
            float a = 0.0f, b = 0.0f;
            if (j < HID) {
                const float* row = Whh + (size_t)(g * HID + j) * HID;
                if (k     < HID) a = row[k];
                if (k + 1 < HID) b = row[k + 1];
            }
            w2[g][m] = pack2(a, b);
        }
    }

    float c = 0.0f;                                  // cell state (lane 0)
    const float* preB = g_pre + (size_t)blk * 32 + w * 4;
    const int    pidx = 64 * w + 2 * lane;           // this thread's poll pair

#pragma unroll 1
    for (int t = 0; t < SEQ; t++) {
        // lanes 0-3 prefetch their own gate's pre-activation (one 16B sector)
        float pvg = 0.0f;
        if (lane < 4)
            pvg = __ldg(preB + (size_t)t * GPAD + lane);

        // ---- poll own 512B chunk of h(t); retry only stale pairs (R4) -----
        {
            const unsigned long long* hb = g_ht[t & 1];
            unsigned long long va, vb;
            ld_pair_cg(&hb[pidx], va, vb);
            for (;;) {
                bool stale = (pkt_tag(va) != t) | (pkt_tag(vb) != t);
                if (!__any_sync(0xffffffffu, stale)) break;
                if (stale) ld_pair_cg(&hb[pidx], va, vb);
            }
            ((float2*)sh_h)[32 * w + lane] = make_float2(pkt_val(va), pkt_val(vb));
        }
        __syncthreads();

        // ---- matvec: 4 gates x 8 packed FMAs from smem --------------------
        unsigned long long acc2[4] = {0ull, 0ull, 0ull, 0ull};
        const float2* sh2 = (const float2*)sh_h;
#pragma unroll
        for (int m = 0; m < 8; m++) {
            float2 hv = sh2[lane + 32 * m];
            unsigned long long h2 = pack2(hv.x, hv.y);
#pragma unroll
            for (int g = 0; g < 4; g++)
                fma2(acc2[g], w2[g][m], h2);
        }
        __syncthreads();    // sh_h fully consumed; safe to refill next iter

        // ---- butterfly reduce (4 gates interleaved; all lanes get sums) ---
        float s[4];
#pragma unroll
        for (int g = 0; g < 4; g++) {
            float lo = __uint_as_float((unsigned)acc2[g]);
            float hi = __uint_as_float((unsigned)(acc2[g] >> 32));
            s[g] = lo + hi;
        }
#pragma unroll
        for (int d = 16; d >= 1; d >>= 1)
#pragma unroll
            for (int g = 0; g < 4; g++)
                s[g] += __shfl_xor_sync(0xffffffffu, s[g], d);

        // ---- parallel activations on lanes 0-3, gather on lane 0 ----------
        if (lane < 4) {
            float x = (lane == 0) ? s[0] : (lane == 1) ? s[1]
                    : (lane == 2) ? s[2] : s[3];
            x += pvg;
            float act = (lane == 2) ? ftanh(x) : fsig(x);
            float gi = __shfl_sync(0x0000000fu, act, 0);
            float gf = __shfl_sync(0x0000000fu, act, 1);
            float gg = __shfl_sync(0x0000000fu, act, 2);
            float go = __shfl_sync(0x0000000fu, act, 3);
            if (lane == 0) {
                c = gf * c + gi * gg;
                float h = go * ftanh(c);
                st_pkt_cg(&g_ht[(t + 1) & 1][j], mk_pkt(t + 1, h));
            }
        }
    }

    // ---------------- final FC: out[20] = fc_w @ h(SEQ) + fc_b (CTA 0) ------
    if (blk == 0) {
        // poll h(SEQ) into smem (same chunked scheme as R4)
        const unsigned long long* hb = g_ht[SEQ & 1];
        unsigned long long va, vb;
        ld_pair_cg(&hb[pidx], va, vb);
        for (;;) {
            bool stale = (pkt_tag(va) != SEQ) | (pkt_tag(vb) != SEQ);
            if (!__any_sync(0xffffffffu, stale)) break;
            if (stale) ld_pair_cg(&hb[pidx], va, vb);
        }
        ((float2*)sh_h)[32 * w + lane] = make_float2(pkt_val(va), pkt_val(vb));
        __syncthreads();

#pragma unroll 1
        for (int o = w; o < 20; o += 8) {
            float a = 0.0f;
#pragma unroll
            for (int m = 0; m < 16; m++) {
                int k = lane + 32 * m;
                if (k < HID) a += fcw[(size_t)o * HID + k] * sh_h[k];
            }
#pragma unroll
            for (int d = 16; d >= 1; d >>= 1)
                a += __shfl_xor_sync(0xffffffffu, a, d);
            if (lane == 0) out[o] = a + fcb[o];
        }
    }
}

// ---------------- launch ----------------------------------------------------
extern "C" void kernel_launch(void* const* d_in, const int* in_sizes, int n_in,
                              void* d_out, int out_size)
{
    const int*   words  = (const int*)  d_in[0];
    const int*   labels = (const int*)  d_in[1];
    const float* ew     = (const float*)d_in[2];
    const float* ee     = (const float*)d_in[3];
    const float* W_ih   = (const float*)d_in[4];
    const float* W_hh   = (const float*)d_in[5];
    const float* b_ih   = (const float*)d_in[6];
    const float* b_hh   = (const float*)d_in[7];
    const float* fc_w   = (const float*)d_in[8];
    const float* fc_b   = (const float*)d_in[9];
    float* out = (float*)d_out;

    k_reset<<<1, JPAD>>>();
    k_gather<<<(SEQ * K_IN) / 1024, 1024>>>(words, labels, ew, ee);
    k_gemm<<<dim3(SEQ / 64, GPAD / 64), 256>>>(W_ih, b_ih, b_hh);
    k_lstm<<<NCTA, CTHR>>>(W_hh, fc_w, fc_b, out);
}